// round 9
// baseline (speedup 1.0000x reference)
#include <cuda_runtime.h>
#include <cstdint>
#define NN 20000
#define EE 320000
using u64 = unsigned long long;

__device__ float g_x[NN*3];
__device__ float g_h[NN*64];
__device__ float g_A[NN*64];
__device__ float g_B[NN*64];
__device__ float g_agg[NN*64];
__device__ float g_xacc[NN*3];
__device__ float g_cnt[NN];
__device__ float g_invc[NN];
__device__ float g_wH[8*4608];  // [layer*2+{W2,C1}] prepped hi images, [64n][72]
__device__ float g_wL[8*4608];  // lo images

__device__ __forceinline__ float silu(float v){ return __fdividef(v,1.f+__expf(-v)); }
__device__ __forceinline__ u64 mk2(float a,float b){u64 r;asm("mov.b64 %0,{%1,%2};":"=l"(r):"f"(a),"f"(b));return r;}
__device__ __forceinline__ u64 ffma2(u64 a,u64 b,u64 c){u64 d;asm("fma.rn.f32x2 %0,%1,%2,%3;":"=l"(d):"l"(a),"l"(b),"l"(c));return d;}
__device__ __forceinline__ float fin(u64 a){float x,y;asm("mov.b64 {%0,%1},%2;":"=f"(x),"=f"(y):"l"(a));return x+y;}
__device__ __forceinline__ float tf32f(float v){uint32_t r;asm("cvt.rna.tf32.f32 %0,%1;":"=r"(r):"f"(v));return __uint_as_float(r);}

// m16n8k8 tf32 mma: d += a@b. a0=(g,q) a1=(g+8,q) a2=(g,q+4) a3=(g+8,q+4)
__device__ __forceinline__ void mma8(float* d, uint32_t a0,uint32_t a1,uint32_t a2,uint32_t a3, uint2 b){
  asm volatile("mma.sync.aligned.m16n8k8.row.col.f32.tf32.tf32.f32 "
    "{%0,%1,%2,%3},{%4,%5,%6,%7},{%8,%9},{%0,%1,%2,%3};"
    : "+f"(d[0]),"+f"(d[1]),"+f"(d[2]),"+f"(d[3])
    : "r"(a0),"r"(a1),"r"(a2),"r"(a3),"r"(b.x),"r"(b.y));
}

// ---- node-side scalar machinery (validated R4/R7) ----
__device__ __forceinline__ void stageW(u64* dst,const float* __restrict__ src,int K,int tid,int nthr){
  int tot=(K/2)*64;
  for(int i=tid;i<tot;i+=nthr){
    int kp=i>>6,c=i&63;
    u64 v=mk2(src[(2*kp)*64+c],src[(2*kp+1)*64+c]);
    dst[(kp<<6)+((c&2)?32:0)+((c>>2)<<1)+(c&1)]=v;
  }
}
__device__ __forceinline__ void ainit(u64* acc,const float* b4,int q){
  float4 b=*(const float4*)&b4[q*4];
#pragma unroll
  for(int r=0;r<4;r++){
    acc[4*r]=mk2(b.x,0.f); acc[4*r+1]=mk2(b.y,0.f);
    acc[4*r+2]=mk2(b.z,0.f); acc[4*r+3]=mk2(b.w,0.f);
  }
}
__device__ __forceinline__ void a0init(u64* acc){
#pragma unroll
  for(int i=0;i<16;i++) acc[i]=0ull;
}
template<int K>
__device__ __forceinline__ void mv8p(const float* vb,int ST,const u64* Wp,int q,u64* acc){
#pragma unroll 8
  for(int kp=0;kp<K/2;kp+=2){
    ulonglong2 a0=*(const ulonglong2*)(vb+2*kp);
    ulonglong2 a1=*(const ulonglong2*)(vb+ST+2*kp);
    ulonglong2 a2=*(const ulonglong2*)(vb+2*ST+2*kp);
    ulonglong2 a3=*(const ulonglong2*)(vb+3*ST+2*kp);
    const u64* wr=Wp+(kp<<6)+2*q;
    ulonglong2 wa0=*(const ulonglong2*)wr;
    ulonglong2 wb0=*(const ulonglong2*)(wr+32);
    ulonglong2 wa1=*(const ulonglong2*)(wr+64);
    ulonglong2 wb1=*(const ulonglong2*)(wr+96);
#define RSTEP(r,A) \
    acc[4*r+0]=ffma2(A.x,wa0.x,acc[4*r+0]); acc[4*r+1]=ffma2(A.x,wa0.y,acc[4*r+1]); \
    acc[4*r+2]=ffma2(A.x,wb0.x,acc[4*r+2]); acc[4*r+3]=ffma2(A.x,wb0.y,acc[4*r+3]); \
    acc[4*r+0]=ffma2(A.y,wa1.x,acc[4*r+0]); acc[4*r+1]=ffma2(A.y,wa1.y,acc[4*r+1]); \
    acc[4*r+2]=ffma2(A.y,wb1.x,acc[4*r+2]); acc[4*r+3]=ffma2(A.y,wb1.y,acc[4*r+3]);
    RSTEP(0,a0) RSTEP(1,a1) RSTEP(2,a2) RSTEP(3,a3)
#undef RSTEP
  }
}

__global__ void k_zero(){
  int i=blockIdx.x*blockDim.x+threadIdx.x;
  if(i<NN) g_cnt[i]=0.f;
  if(i<NN*3) g_xacc[i]=0.f;
}
__global__ void k_count(const int* __restrict__ erow){
  int e=blockIdx.x*blockDim.x+threadIdx.x;
  if(e<EE) atomicAdd(&g_cnt[erow[e]],1.f);
}

// prep: W[k][n] (row-major) -> Wt[n][p(k)] hi/lo, stride 72, k-permuted so
// frag pairs (k, k+4) are adjacent: p(k) = (k&~7) + 2*(k&3) + ((k>>2)&1)
__global__ void k_prep(const float* __restrict__ ew2,const float* __restrict__ cw1){
  int i=blockIdx.x*blockDim.x+threadIdx.x;
  if(i>=8*4096) return;
  int l=i>>13, m=(i>>12)&1, j=i&4095, k=j>>6, n=j&63;
  const float* src=(m?cw1:ew2)+l*4096;
  float v=src[k*64+n];
  float hi=tf32f(v), lo=v-hi;
  int p=(k&~7)+((k&3)<<1)+((k>>2)&1);
  int d=(l*2+m)*4608 + n*72 + p;
  g_wH[d]=hi; g_wL[d]=lo;
}

// h0=h16@Wi+bi ; A=h0@EA+eb ; B=h0@EB ; init x, invc, agg=0  (validated)
__global__ void __launch_bounds__(256) k_embed(
    const float* __restrict__ h16,const float* __restrict__ xin,
    const float* __restrict__ Wi,const float* __restrict__ bi,
    const float* __restrict__ EA,const float* __restrict__ eb,
    const float* __restrict__ EB){
  extern __shared__ char sr[];
  u64* sWip=(u64*)sr; u64* sEAp=(u64*)(sr+4096); u64* sEBp=(u64*)(sr+20480);
  float* sbi=(float*)(sr+36864); float* seb=(float*)(sr+37120);
  float* vbase=(float*)(sr+37376);
  const int tid=threadIdx.x,wid=tid>>5,lane=tid&31,q=lane&15,g2=lane>>4;
  stageW(sWip,Wi,16,tid,256);
  stageW(sEAp,EA,64,tid,256);
  stageW(sEBp,EB,64,tid,256);
  if(tid<64){sbi[tid]=bi[tid];seb[tid]=eb[tid];}
  float* vb=vbase+wid*(8*84);
  int nbase=blockIdx.x*64+wid*8;
#pragma unroll
  for(int t=0;t<4;t++){
    int e=t*2+g2,n=nbase+e;
    if(q<4){
      float4 v=make_float4(0,0,0,0);
      if(n<NN) v=*(const float4*)&h16[n*16+q*4];
      *(float4*)&vb[e*84+q*4]=v;
    }
    if(n<NN) *(float4*)&g_agg[n*64+q*4]=make_float4(0,0,0,0);
  }
  if(lane<8){int n=nbase+lane; if(n<NN) g_invc[n]=__fdividef(1.f,fmaxf(g_cnt[n],1.f));}
  if(lane<24){int e=lane/3,d=lane-3*(lane/3),n=nbase+e; if(n<NN) g_x[n*3+d]=xin[n*3+d];}
  __syncthreads();
  u64 acc[16];
  ainit(acc,sbi,q);
  mv8p<16>(vb+g2*4*84,84,sWip,q,acc);
  __syncwarp();
#pragma unroll
  for(int r=0;r<4;r++){
    int e=g2*4+r,n=nbase+e;
    float4 h0=make_float4(fin(acc[4*r]),fin(acc[4*r+1]),fin(acc[4*r+2]),fin(acc[4*r+3]));
    *(float4*)&vb[e*84+16+q*4]=h0;
    if(n<NN) *(float4*)&g_h[n*64+q*4]=h0;
  }
  __syncwarp();
  ainit(acc,seb,q);
  mv8p<64>(vb+g2*4*84+16,84,sEAp,q,acc);
#pragma unroll
  for(int r=0;r<4;r++){
    int n=nbase+g2*4+r;
    if(n<NN) *(float4*)&g_A[n*64+q*4]=make_float4(fin(acc[4*r]),fin(acc[4*r+1]),fin(acc[4*r+2]),fin(acc[4*r+3]));
  }
  a0init(acc);
  mv8p<64>(vb+g2*4*84+16,84,sEBp,q,acc);
#pragma unroll
  for(int r=0;r<4;r++){
    int n=nbase+g2*4+r;
    if(n<NN) *(float4*)&g_B[n*64+q*4]=make_float4(fin(acc[4*r]),fin(acc[4*r+1]),fin(acc[4*r+2]),fin(acc[4*r+3]));
  }
}

// ---- tensor-core edge kernel: 128 edges/CTA, 8 warps, 16 edges/warp, 3xTF32 mma.sync ----
__global__ void __launch_bounds__(256) k_edge(
    const int* __restrict__ erow,const int* __restrict__ ecol,int layer,
    const float* __restrict__ w1c,const float* __restrict__ b2,
    const float* __restrict__ cb1,const float* __restrict__ cw2){
  extern __shared__ float sf[];
  float* sWh=sf; float* sWl=sf+4608; float* sCh=sf+9216; float* sCl=sf+13824;
  float* sb=sf+18432;
  const int tid=threadIdx.x,wid=tid>>5,lane=tid&31;
  float* aSh=sf+18688+wid*2304; float* aSl=aSh+1152;
  float* meta=sf+37120+wid*128;
  float* dfb=meta; float* rad=meta+48; float* icb=meta+64;
  int* rw=(int*)(meta+80); int* cl=(int*)(meta+96); float* phi=meta+112;
  {
    const float4* h0=(const float4*)(g_wH+(layer*2)*4608);
    const float4* l0=(const float4*)(g_wL+(layer*2)*4608);
    const float4* h1=(const float4*)(g_wH+(layer*2+1)*4608);
    const float4* l1=(const float4*)(g_wL+(layer*2+1)*4608);
    float4* dWh=(float4*)sWh; float4* dWl=(float4*)sWl;
    float4* dCh=(float4*)sCh; float4* dCl=(float4*)sCl;
    for(int i=tid;i<1152;i+=256){ dWh[i]=h0[i]; dWl[i]=l0[i]; dCh[i]=h1[i]; dCl[i]=l1[i]; }
  }
  if(tid<64){ sb[tid]=w1c[tid]; sb[64+tid]=b2[tid]; sb[128+tid]=cb1[tid]; sb[192+tid]=cw2[tid]; }
  int ebase=blockIdx.x*128+wid*16;
  if(lane<16){
    int e=ebase+lane,r=erow[e],c=ecol[e];
    rw[lane]=r; cl[lane]=c;
    float dx=g_x[r*3]-g_x[c*3],dy=g_x[r*3+1]-g_x[c*3+1],dz=g_x[r*3+2]-g_x[c*3+2];
    dfb[lane*3]=dx; dfb[lane*3+1]=dy; dfb[lane*3+2]=dz;
    rad[lane]=dx*dx+dy*dy+dz*dz; icb[lane]=g_invc[r];
  }
  __syncthreads();
  // phase1: m1 = silu(A[r]+B[c]+rad*w1c) -> aS hi/lo, permuted layout [e][72]
  {
    int e=lane>>1, half=lane&1;
    int r=rw[e], c=cl[e]; float rd=rad[e];
#pragma unroll
    for(int o=0;o<4;o++){
      int kb=half*32+o*8;
      float va[8],vb8[8];
      *(float4*)&va[0]=*(const float4*)&g_A[r*64+kb];
      *(float4*)&va[4]=*(const float4*)&g_A[r*64+kb+4];
      *(float4*)&vb8[0]=*(const float4*)&g_B[c*64+kb];
      *(float4*)&vb8[4]=*(const float4*)&g_B[c*64+kb+4];
      float vv[8];
#pragma unroll
      for(int j=0;j<8;j++) vv[j]=silu(va[j]+vb8[j]+rd*sb[kb+j]);
#pragma unroll
      for(int j=0;j<4;j++){
        float h0=tf32f(vv[j]), h1=tf32f(vv[j+4]);
        int w=e*72+kb+2*j;
        *(float2*)&aSh[w]=make_float2(h0,h1);
        *(float2*)&aSl[w]=make_float2(vv[j]-h0,vv[j+4]-h1);
      }
    }
  }
  __syncwarp();
  const int gq=lane>>2, q=lane&3;
  float acc[8][4];
  // ---- matvec1: m = silu(m1 @ W2 + b2) ----
#pragma unroll
  for(int nt=0;nt<8;nt++){acc[nt][0]=0;acc[nt][1]=0;acc[nt][2]=0;acc[nt][3]=0;}
#pragma unroll
  for(int kc=0;kc<8;kc++){
    int kb=kc*8, ar=gq*72+kb+2*q;
    uint2 ah01=*(const uint2*)&aSh[ar], ah23=*(const uint2*)&aSh[ar+576];
    uint2 al01=*(const uint2*)&aSl[ar], al23=*(const uint2*)&aSl[ar+576];
#pragma unroll
    for(int nt=0;nt<8;nt++){
      int br=(nt*8+gq)*72+kb+2*q;
      uint2 bh=*(const uint2*)&sWh[br];
      uint2 bl=*(const uint2*)&sWl[br];
      mma8(acc[nt],ah01.x,ah23.x,ah01.y,ah23.y,bh);
      mma8(acc[nt],al01.x,al23.x,al01.y,al23.y,bh);
      mma8(acc[nt],ah01.x,ah23.x,ah01.y,ah23.y,bl);
    }
  }
  __syncwarp();
  // epilogue1: silu+bias, red into agg, restage hi/lo
  {
    int r0=rw[gq], r1=rw[gq+8];
#pragma unroll
    for(int nt=0;nt<8;nt++){
      int c0=nt*8+2*q;
      float m00=silu(acc[nt][0]+sb[64+c0]);
      float m01=silu(acc[nt][1]+sb[64+c0+1]);
      float m10=silu(acc[nt][2]+sb[64+c0]);
      float m11=silu(acc[nt][3]+sb[64+c0+1]);
      asm volatile("red.global.add.v2.f32 [%0],{%1,%2};"::"l"(&g_agg[r0*64+c0]),"f"(m00),"f"(m01):"memory");
      asm volatile("red.global.add.v2.f32 [%0],{%1,%2};"::"l"(&g_agg[r1*64+c0]),"f"(m10),"f"(m11):"memory");
      int p0=nt*8+(((2*q)&3)<<1)+(q>>1);
      float h;
      h=tf32f(m00); aSh[gq*72+p0]=h;       aSl[gq*72+p0]=m00-h;
      h=tf32f(m01); aSh[gq*72+p0+2]=h;     aSl[gq*72+p0+2]=m01-h;
      h=tf32f(m10); aSh[(gq+8)*72+p0]=h;   aSl[(gq+8)*72+p0]=m10-h;
      h=tf32f(m11); aSh[(gq+8)*72+p0+2]=h; aSl[(gq+8)*72+p0+2]=m11-h;
    }
  }
  __syncwarp();
  // ---- matvec2: t = m @ CW1 + cb1 ----
#pragma unroll
  for(int nt=0;nt<8;nt++){acc[nt][0]=0;acc[nt][1]=0;acc[nt][2]=0;acc[nt][3]=0;}
#pragma unroll
  for(int kc=0;kc<8;kc++){
    int kb=kc*8, ar=gq*72+kb+2*q;
    uint2 ah01=*(const uint2*)&aSh[ar], ah23=*(const uint2*)&aSh[ar+576];
    uint2 al01=*(const uint2*)&aSl[ar], al23=*(const uint2*)&aSl[ar+576];
#pragma unroll
    for(int nt=0;nt<8;nt++){
      int br=(nt*8+gq)*72+kb+2*q;
      uint2 bh=*(const uint2*)&sCh[br];
      uint2 bl=*(const uint2*)&sCl[br];
      mma8(acc[nt],ah01.x,ah23.x,ah01.y,ah23.y,bh);
      mma8(acc[nt],al01.x,al23.x,al01.y,al23.y,bh);
      mma8(acc[nt],ah01.x,ah23.x,ah01.y,ah23.y,bl);
    }
  }
  // epilogue2: phi_e = sum_c silu(t+cb1)*cw2 ; coord atomics
  {
    float pA=0.f,pB=0.f;
#pragma unroll
    for(int nt=0;nt<8;nt++){
      int c0=nt*8+2*q;
      pA+=silu(acc[nt][0]+sb[128+c0])*sb[192+c0]+silu(acc[nt][1]+sb[128+c0+1])*sb[192+c0+1];
      pB+=silu(acc[nt][2]+sb[128+c0])*sb[192+c0]+silu(acc[nt][3]+sb[128+c0+1])*sb[192+c0+1];
    }
    pA+=__shfl_xor_sync(0xffffffffu,pA,1); pA+=__shfl_xor_sync(0xffffffffu,pA,2);
    pB+=__shfl_xor_sync(0xffffffffu,pB,1); pB+=__shfl_xor_sync(0xffffffffu,pB,2);
    if(q==0){ phi[gq]=pA; phi[gq+8]=pB; }
  }
  __syncwarp();
  if(lane<16){
    float s=phi[lane]*icb[lane];
    int r=rw[lane];
    atomicAdd(&g_xacc[r*3+0],dfb[lane*3+0]*s);
    atomicAdd(&g_xacc[r*3+1],dfb[lane*3+1]*s);
    atomicAdd(&g_xacc[r*3+2],dfb[lane*3+2]*s);
  }
}

// node: x+=xacc; t=silu([h|agg]@NW1+nb1); h+=t@NW2+nb2; next-layer A/B or final out (validated)
__global__ void __launch_bounds__(256) k_node(
    const float* __restrict__ NW1,const float* __restrict__ nb1,
    const float* __restrict__ NW2,const float* __restrict__ nb2,
    const float* __restrict__ WA,const float* __restrict__ ba,
    const float* __restrict__ WB,int last,float* __restrict__ outp){
  extern __shared__ char sr[];
  u64* sN1p=(u64*)sr;
  u64* sN2p=(u64*)(sr+32768);
  u64* sAp =(u64*)(sr+49152);
  float* snb1=(float*)(sr+65536); float* snb2=(float*)(sr+65792);
  float* sba=(float*)(sr+66048);
  float* vbase=(float*)(sr+66304);
  const int tid=threadIdx.x,wid=tid>>5,lane=tid&31,q=lane&15,g2=lane>>4;
  stageW(sN1p,NW1,128,tid,256);
  stageW(sN2p,NW2,64,tid,256);
  stageW(sAp,WA,64,tid,256);
  if(tid<64){snb1[tid]=nb1[tid];snb2[tid]=nb2[tid];sba[tid]=ba[tid];}
  float* vb=vbase+wid*1056;
  int nbase=blockIdx.x*64+wid*8;
#pragma unroll
  for(int t=0;t<4;t++){
    int e=t*2+g2,n=nbase+e;
    float4 h4=make_float4(0,0,0,0),a4=make_float4(0,0,0,0);
    if(n<NN){
      h4=*(const float4*)&g_h[n*64+q*4];
      a4=*(const float4*)&g_agg[n*64+q*4];
      *(float4*)&g_agg[n*64+q*4]=make_float4(0,0,0,0);
    }
    *(float4*)&vb[e*132+q*4]=h4;
    *(float4*)&vb[e*132+64+q*4]=a4;
  }
  if(lane<24){
    int e=lane/3,d=lane-3*(lane/3),n=nbase+e;
    if(n<NN){
      float nx=g_x[n*3+d]+g_xacc[n*3+d];
      g_x[n*3+d]=nx; g_xacc[n*3+d]=0.f;
      if(last) outp[NN*64+n*3+d]=nx;
    }
  }
  __syncthreads();
  u64 acc[16];
  ainit(acc,snb1,q);
  mv8p<128>(vb+g2*4*132,132,sN1p,q,acc);
  __syncwarp();
#pragma unroll
  for(int r=0;r<4;r++){
    int e=g2*4+r;
    *(float4*)&vb[e*132+64+q*4]=make_float4(
      silu(fin(acc[4*r])),silu(fin(acc[4*r+1])),silu(fin(acc[4*r+2])),silu(fin(acc[4*r+3])));
  }
  __syncthreads();
  if(!last) stageW(sN1p,WB,64,tid,256);
  ainit(acc,snb2,q);
  mv8p<64>(vb+g2*4*132+64,132,sN2p,q,acc);
  __syncwarp();
#pragma unroll
  for(int r=0;r<4;r++){
    int e=g2*4+r,n=nbase+e;
    float4 ho=*(const float4*)&vb[e*132+q*4];
    float4 hn=make_float4(ho.x+fin(acc[4*r]),ho.y+fin(acc[4*r+1]),
                          ho.z+fin(acc[4*r+2]),ho.w+fin(acc[4*r+3]));
    *(float4*)&vb[e*132+q*4]=hn;
    if(n<NN) *(float4*)&g_h[n*64+q*4]=hn;
  }
  __syncthreads();
  ainit(acc,sba,q);
  mv8p<64>(vb+g2*4*132,132,sAp,q,acc);
  if(last){
#pragma unroll
    for(int r=0;r<4;r++){
      int n=nbase+g2*4+r;
      if(n<NN) *(float4*)&outp[n*64+q*4]=make_float4(fin(acc[4*r]),fin(acc[4*r+1]),fin(acc[4*r+2]),fin(acc[4*r+3]));
    }
  } else {
#pragma unroll
    for(int r=0;r<4;r++){
      int n=nbase+g2*4+r;
      if(n<NN) *(float4*)&g_A[n*64+q*4]=make_float4(fin(acc[4*r]),fin(acc[4*r+1]),fin(acc[4*r+2]),fin(acc[4*r+3]));
    }
    a0init(acc);
    mv8p<64>(vb+g2*4*132,132,sN1p,q,acc);
#pragma unroll
    for(int r=0;r<4;r++){
      int n=nbase+g2*4+r;
      if(n<NN) *(float4*)&g_B[n*64+q*4]=make_float4(fin(acc[4*r]),fin(acc[4*r+1]),fin(acc[4*r+2]),fin(acc[4*r+3]));
    }
  }
}

extern "C" void kernel_launch(void* const* d_in,const int* in_sizes,int n_in,
                              void* d_out,int out_size){
  const float* h16=(const float*)d_in[0];
  const float* xin=(const float*)d_in[1];
  const int*   ei =(const int*  )d_in[2];
  const float* Wi =(const float*)d_in[3];
  const float* bi =(const float*)d_in[4];
  const float* ew1=(const float*)d_in[5];
  const float* eb1=(const float*)d_in[6];
  const float* ew2=(const float*)d_in[7];
  const float* eb2=(const float*)d_in[8];
  const float* cw1=(const float*)d_in[9];
  const float* cb1=(const float*)d_in[10];
  const float* cw2=(const float*)d_in[11];
  const float* nw1=(const float*)d_in[12];
  const float* nb1=(const float*)d_in[13];
  const float* nw2=(const float*)d_in[14];
  const float* nb2=(const float*)d_in[15];
  const float* Wo =(const float*)d_in[16];
  const float* bo =(const float*)d_in[17];
  float* outp=(float*)d_out;
  const int* erow=ei; const int* ecol=ei+EE;

  const int SME=58880, SMEDGE=(37120+8*128)*4, SMN=100096;
  cudaFuncSetAttribute(k_embed,cudaFuncAttributeMaxDynamicSharedMemorySize,SME);
  cudaFuncSetAttribute(k_edge, cudaFuncAttributeMaxDynamicSharedMemorySize,SMEDGE);
  cudaFuncSetAttribute(k_node, cudaFuncAttributeMaxDynamicSharedMemorySize,SMN);

  const int NB=(NN+63)/64;
  k_zero<<<(NN*3+255)/256,256>>>();
  k_count<<<(EE+255)/256,256>>>(erow);
  k_prep<<<128,256>>>(ew2,cw1);
  k_embed<<<NB,256,SME>>>(h16,xin,Wi,bi,ew1,eb1,ew1+64*64);
  for(int l=0;l<4;l++){
    k_edge<<<EE/128,256,SMEDGE>>>(erow,ecol,l,ew1+l*129*64+128*64,eb2+l*64,
                                  cb1+l*64,cw2+l*64);
    int last=(l==3);
    const float* WA = last ? Wo : ew1+(l+1)*129*64;
    const float* ba = last ? bo : eb1+(l+1)*64;
    const float* WB = last ? Wo : WA+64*64;
    k_node<<<NB,256,SMN>>>(nw1+l*128*64,nb1+l*64,nw2+l*4096,nb2+l*64,WA,ba,WB,last,outp);
  }
}